// round 2
// baseline (speedup 1.0000x reference)
#include <cuda_runtime.h>
#include <cstdint>

typedef unsigned long long ull;

#define BB   512
#define TT   2000
#define HH   128
#define NI   13
#define GG   512          // 4*H gate columns
#define BC   4            // batch per CTA
#define NBLK (BB/BC)      // 128 CTAs
#define NTHR 256
#define WS_K 104          // weight k-rows cached in smem (208 KB)

// -------- device scratch (static: allocation-free rule) --------
__device__ __align__(16) float d_Wt0[(NI+HH)*GG];    // layer0 combined transposed [141][512]
__device__ __align__(16) float d_Wt1[(HH+HH)*GG];    // layer1 combined transposed [256][512]
__device__ float d_b0[GG];
__device__ float d_b1[GG];
__device__ float d_h1[(size_t)BB*TT*HH];             // layer0 hidden sequence (524 MB)
__device__ float d_h2last[BB*HH];

// -------- packed f32x2 helpers --------
__device__ __forceinline__ ull pack2(float x, float y){
    ull r; asm("mov.b64 %0,{%1,%2};" : "=l"(r) : "f"(x), "f"(y)); return r;
}
__device__ __forceinline__ ull dup2(float x){ return pack2(x, x); }
__device__ __forceinline__ ull ffma2(ull a, ull b, ull c){
    ull d; asm("fma.rn.f32x2 %0,%1,%2,%3;" : "=l"(d) : "l"(a), "l"(b), "l"(c)); return d;
}

__device__ __forceinline__ float sigf(float x){
    return __fdividef(1.0f, 1.0f + __expf(-x));
}
__device__ __forceinline__ float tanh_(float x){
    return 1.0f - __fdividef(2.0f, __expf(2.0f*x) + 1.0f);
}

// -------- weight prep: transpose + combine, bias sums --------
__global__ void prep_kernel(const float* __restrict__ Wih0, const float* __restrict__ Whh0,
                            const float* __restrict__ bih0, const float* __restrict__ bhh0,
                            const float* __restrict__ Wih1, const float* __restrict__ Whh1,
                            const float* __restrict__ bih1, const float* __restrict__ bhh1)
{
    int stride = gridDim.x * blockDim.x;
    int i0 = blockIdx.x * blockDim.x + threadIdx.x;
    for (int i = i0; i < (NI+HH)*GG; i += stride){
        int k = i / GG, j = i - k*GG;
        d_Wt0[i] = (k < NI) ? Wih0[j*NI + k] : Whh0[j*HH + (k-NI)];
    }
    for (int i = i0; i < (HH+HH)*GG; i += stride){
        int k = i / GG, j = i - k*GG;
        d_Wt1[i] = (k < HH) ? Wih1[j*HH + k] : Whh1[j*HH + (k-HH)];
    }
    for (int i = i0; i < GG; i += stride){
        d_b0[i] = bih0[i] + bhh0[i];
        d_b1[i] = bih1[i] + bhh1[i];
    }
}

// -------- persistent LSTM layer kernel --------
// Thread tid owns gate cols (2*tid, 2*tid+1) for 4 batches during the GEMV,
// and (h-index tid&127, batches 2*(tid>>7)+{0,1}) during the state update.
// Weight residency: rows [0,WS) in smem, [WS,WS+RR) in registers, rest via L2.
template<int LAYER>
__global__ void __launch_bounds__(NTHR, 1) lstm_layer(const float* __restrict__ xin_param)
{
    constexpr int IN = (LAYER == 0) ? NI : HH;
    constexpr int K  = IN + HH;
    constexpr int WS = (WS_K < K) ? WS_K : K;
    constexpr int RR = (LAYER == 0) ? (K - WS) : 88;     // register-cached rows
    constexpr int S0 = WS + RR;                          // first L2-streamed row

    extern __shared__ ull smem_u[];
    ull* ws2 = smem_u;                 // [WS][256] weight ull per thread-colpair
    ull* hd2 = ws2 + WS*256;           // [K][4] dup-packed inputs/h per batch
    ull* gs2 = hd2 + (size_t)K*4;      // [4][256] gate pre-activations
    float* gsf = (float*)gs2;          // float view [b][512]

    const float* Wt  = (LAYER == 0) ? d_Wt0 : d_Wt1;
    const ull*   wt2 = (const ull*)Wt;
    const float* bia = (LAYER == 0) ? d_b0  : d_b1;
    const float* xin = (LAYER == 0) ? xin_param : d_h1;

    const int tid = threadIdx.x;
    const int b0  = blockIdx.x * BC;

    // tier 1: smem weight cache
    {
        const float4* src = (const float4*)Wt;
        float4* dst = (float4*)ws2;
        for (int i = tid; i < WS*(GG/4); i += NTHR) dst[i] = src[i];
    }
    // tier 2: register weight cache (this thread's 2 cols of rows WS..WS+RR-1)
    ull wreg[RR];
    #pragma unroll
    for (int r = 0; r < RR; ++r) wreg[r] = wt2[(size_t)(WS + r)*256 + tid];

    // zero recurrent-h region of hd
    for (int i = tid; i < HH*4; i += NTHR) hd2[IN*4 + i] = 0ull;

    const ull bi = pack2(bia[2*tid], bia[2*tid + 1]);

    float cst[2] = {0.f, 0.f};
    const int dj  = tid & (HH-1);        // h index for phase D
    const int db  = (tid >> 7) * 2;      // first of 2 batches for phase D

    __syncthreads();

    for (int t = 0; t < TT; ++t) {
        // ---- phase A: stage this step's input slice (dup-packed) ----
        for (int idx = tid; idx < BC*IN; idx += NTHR) {
            int b = idx / IN;
            int k = idx - b*IN;
            hd2[k*4 + b] = dup2(xin[((size_t)(b0 + b)*TT + t)*IN + k]);
        }
        __syncthreads();   // covers phase-A writes AND prev-step recurrent-h writes

        // ---- phase B: gate pre-activations ----
        ull a0 = bi, a1 = bi, a2 = bi, a3 = bi;
        const ulonglong2* hdq = (const ulonglong2*)hd2;

        // register rows (no weight load at all)
        #pragma unroll
        for (int r = 0; r < RR; ++r) {
            ulonglong2 hA = hdq[(WS + r)*2];
            ulonglong2 hB = hdq[(WS + r)*2 + 1];
            a0 = ffma2(hA.x, wreg[r], a0);  a1 = ffma2(hA.y, wreg[r], a1);
            a2 = ffma2(hB.x, wreg[r], a2);  a3 = ffma2(hB.y, wreg[r], a3);
        }
        // L2-streamed rows (layer1 only) — issued here so the smem part below
        // plus the co-resident warp's FMA traffic hides L2 latency
        if (S0 < K) {
            #pragma unroll 8
            for (int k = S0; k < K; ++k) {
                ull w = __ldg(&wt2[(size_t)k*256 + tid]);
                ulonglong2 hA = hdq[k*2];
                ulonglong2 hB = hdq[k*2 + 1];
                a0 = ffma2(hA.x, w, a0);  a1 = ffma2(hA.y, w, a1);
                a2 = ffma2(hB.x, w, a2);  a3 = ffma2(hB.y, w, a3);
            }
        }
        // smem rows
        #pragma unroll 4
        for (int k = 0; k < WS; ++k) {
            ull w = ws2[k*256 + tid];
            ulonglong2 hA = hdq[k*2];
            ulonglong2 hB = hdq[k*2 + 1];
            a0 = ffma2(hA.x, w, a0);  a1 = ffma2(hA.y, w, a1);
            a2 = ffma2(hB.x, w, a2);  a3 = ffma2(hB.y, w, a3);
        }

        // ---- phase C: publish gate pre-activations ----
        gs2[0*256 + tid] = a0;
        gs2[1*256 + tid] = a1;
        gs2[2*256 + tid] = a2;
        gs2[3*256 + tid] = a3;
        __syncthreads();

        // ---- phase D: gates + state update (thread -> (dj, 2 batches)) ----
        #pragma unroll
        for (int q = 0; q < 2; ++q) {
            int b = db + q;
            float gi = gsf[b*GG +          dj];
            float gf = gsf[b*GG +   HH  +  dj];
            float gg = gsf[b*GG + 2*HH  +  dj];
            float go = gsf[b*GG + 3*HH  +  dj];
            float ig = sigf(gi);
            float fg = sigf(gf);
            float gv = tanh_(gg);
            float og = sigf(go);
            float c  = fg*cst[q] + ig*gv;
            cst[q] = c;
            float h = og * tanh_(c);
            hd2[(IN + dj)*4 + b] = dup2(h);
            if (LAYER == 0) {
                d_h1[((size_t)(b0 + b)*TT + t)*HH + dj] = h;
            } else {
                if (t == TT-1) d_h2last[(b0 + b)*HH + dj] = h;
            }
        }
        // next iteration's phase-A sync orders D's hd2 writes before the k-loop
    }
}

// -------- final FC: out[b][c] = h2last[b] . Wfc[c] + bfc[c] --------
__global__ void fc_kernel(const float* __restrict__ Wfc, const float* __restrict__ bfc,
                          float* __restrict__ out)
{
    int b = blockIdx.x;
    int c = threadIdx.x >> 5;
    int l = threadIdx.x & 31;
    float s = 0.f;
    #pragma unroll
    for (int q = 0; q < 4; ++q) {
        int j = l + 32*q;
        s += d_h2last[b*HH + j] * Wfc[c*HH + j];
    }
    #pragma unroll
    for (int o = 16; o; o >>= 1) s += __shfl_xor_sync(0xffffffffu, s, o);
    if (l == 0) out[b*4 + c] = s + bfc[c];
}

// -------- launch --------
extern "C" void kernel_launch(void* const* d_in, const int* in_sizes, int n_in,
                              void* d_out, int out_size)
{
    const float* x    = (const float*)d_in[0];
    const float* Wih0 = (const float*)d_in[1];
    const float* Whh0 = (const float*)d_in[2];
    const float* bih0 = (const float*)d_in[3];
    const float* bhh0 = (const float*)d_in[4];
    const float* Wih1 = (const float*)d_in[5];
    const float* Whh1 = (const float*)d_in[6];
    const float* bih1 = (const float*)d_in[7];
    const float* bhh1 = (const float*)d_in[8];
    const float* Wfc  = (const float*)d_in[9];
    const float* bfc  = (const float*)d_in[10];
    float* out = (float*)d_out;

    // smem bytes: (WS*256 + K*4 + 4*256) ull
    constexpr int K0 = NI + HH, K1 = HH + HH;
    constexpr int SMEM0 = (WS_K*256 + K0*4 + 4*256) * 8;   // 225,696 B
    constexpr int SMEM1 = (WS_K*256 + K1*4 + 4*256) * 8;   // 229,376 B

    cudaFuncSetAttribute(lstm_layer<0>, cudaFuncAttributeMaxDynamicSharedMemorySize, SMEM0);
    cudaFuncSetAttribute(lstm_layer<1>, cudaFuncAttributeMaxDynamicSharedMemorySize, SMEM1);

    prep_kernel<<<256, 256>>>(Wih0, Whh0, bih0, bhh0, Wih1, Whh1, bih1, bhh1);
    lstm_layer<0><<<NBLK, NTHR, SMEM0>>>(x);
    lstm_layer<1><<<NBLK, NTHR, SMEM1>>>(nullptr);
    fc_kernel<<<BB, 128>>>(Wfc, bfc, out);
}

// round 3
// speedup vs baseline: 1.2140x; 1.2140x over previous
#include <cuda_runtime.h>
#include <cstdint>

typedef unsigned long long ull;

#define BB   512
#define TT   2000
#define HH   128
#define NI   13
#define GG   512          // 4*H gate columns
#define BC   4            // batch per CTA
#define NBLK (BB/BC)      // 128 CTAs
#define NTHR 256
#define WS_K 104          // weight k-rows cached in smem (208 KB)

// -------- device scratch (static: allocation-free rule) --------
__device__ __align__(16) float d_Wt0[(NI+HH)*GG];    // layer0 combined transposed [141][512]
__device__ __align__(16) float d_Wt1[(HH+HH)*GG];    // layer1 combined transposed [256][512]
__device__ float d_b0[GG];
__device__ float d_b1[GG];
__device__ float d_h1[(size_t)BB*TT*HH];             // layer0 hidden sequence (524 MB)

// -------- packed f32x2 helpers --------
__device__ __forceinline__ ull pack2(float x, float y){
    ull r; asm("mov.b64 %0,{%1,%2};" : "=l"(r) : "f"(x), "f"(y)); return r;
}
__device__ __forceinline__ ull dup2(float x){ return pack2(x, x); }
__device__ __forceinline__ ull ffma2(ull a, ull b, ull c){
    ull d; asm("fma.rn.f32x2 %0,%1,%2,%3;" : "=l"(d) : "l"(a), "l"(b), "l"(c)); return d;
}

// accurate (expf-based) activations for the c-accumulation path
__device__ __forceinline__ float sigf(float x){
    return __fdividef(1.0f, 1.0f + __expf(-x));
}
__device__ __forceinline__ float tanh_(float x){
    return 1.0f - __fdividef(2.0f, __expf(2.0f*x) + 1.0f);
}
// HW tanh (MUFU.TANH) for the output path (no long-horizon accumulation)
__device__ __forceinline__ float tanhap(float x){
    float y; asm("tanh.approx.f32 %0,%1;" : "=f"(y) : "f"(x)); return y;
}

// -------- weight prep: transpose + combine, bias sums --------
__global__ void prep_kernel(const float* __restrict__ Wih0, const float* __restrict__ Whh0,
                            const float* __restrict__ bih0, const float* __restrict__ bhh0,
                            const float* __restrict__ Wih1, const float* __restrict__ Whh1,
                            const float* __restrict__ bih1, const float* __restrict__ bhh1)
{
    int stride = gridDim.x * blockDim.x;
    int i0 = blockIdx.x * blockDim.x + threadIdx.x;
    for (int i = i0; i < (NI+HH)*GG; i += stride){
        int k = i / GG, j = i - k*GG;
        d_Wt0[i] = (k < NI) ? Wih0[j*NI + k] : Whh0[j*HH + (k-NI)];
    }
    for (int i = i0; i < (HH+HH)*GG; i += stride){
        int k = i / GG, j = i - k*GG;
        d_Wt1[i] = (k < HH) ? Wih1[j*HH + k] : Whh1[j*HH + (k-HH)];
    }
    for (int i = i0; i < GG; i += stride){
        d_b0[i] = bih0[i] + bhh0[i];
        d_b1[i] = bih1[i] + bhh1[i];
    }
}

// -------- persistent LSTM layer kernel --------
// Thread tid owns gate cols (2*tid, 2*tid+1) for 4 batches in the GEMV,
// and (h-index tid&127, batches 2*(tid>>7)+{0,1}) in the state update.
// Weight residency: rows [0,WS) smem, [WS,WS+RR) registers, rest streamed from
// L2 interleaved with the smem-tier FMAs so LTS delivery hides under compute.
template<int LAYER>
__global__ void __launch_bounds__(NTHR, 1) lstm_layer(const float* __restrict__ xin_param,
                                                      const float* __restrict__ Wfc,
                                                      const float* __restrict__ bfc,
                                                      float* __restrict__ out)
{
    constexpr int IN = (LAYER == 0) ? NI : HH;
    constexpr int K  = IN + HH;
    constexpr int WS = WS_K;                             // 104 smem rows
    constexpr int RR = (LAYER == 0) ? (K - WS) : 80;     // register rows
    constexpr int S0 = WS + RR;                          // first streamed row
    constexpr int NS = K - S0;                           // streamed rows (0 or 72)
    constexpr int CH = 4;                                // stream chunk rows
    constexpr int NCH = (NS > 0) ? NS/CH : 0;            // 18 for layer1
    constexpr int SEG = 5;                               // smem rows per interleave segment

    extern __shared__ ull smem_u[];
    ull* ws2 = smem_u;                 // [WS][256] weight ull per thread-colpair
    ull* hd2 = ws2 + WS*256;           // [K][4] dup-packed inputs/h per batch
    ull* gs2 = hd2 + (size_t)K*4;      // [4][256] gate pre-activations
    float* gsf = (float*)gs2;          // float view [b][512]

    const float* Wt  = (LAYER == 0) ? d_Wt0 : d_Wt1;
    const ull*   wt2 = (const ull*)Wt;
    const float* bia = (LAYER == 0) ? d_b0  : d_b1;
    const float* xin = (LAYER == 0) ? xin_param : d_h1;

    const int tid = threadIdx.x;
    const int b0  = blockIdx.x * BC;

    // tier 1: smem weight cache (coalesced from transposed layout)
    {
        const float4* src = (const float4*)Wt;
        float4* dst = (float4*)ws2;
        for (int i = tid; i < WS*(GG/4); i += NTHR) dst[i] = src[i];
    }
    // tier 2: register weight cache
    ull wreg[RR];
    #pragma unroll
    for (int r = 0; r < RR; ++r) wreg[r] = wt2[(size_t)(WS + r)*256 + tid];

    // zero recurrent-h region of hd
    for (int i = tid; i < HH*4; i += NTHR) hd2[IN*4 + i] = 0ull;

    const ull bi = pack2(bia[2*tid], bia[2*tid + 1]);

    float cst[2] = {0.f, 0.f};
    const int dj  = tid & (HH-1);        // h index for phase D
    const int db  = (tid >> 7) * 2;      // first of 2 batches for phase D

    // ---- xin prefetch state ----
    // layer1: thread -> (b = tid>>6, k = 2*(tid&63)), float2 per step
    // layer0: thread tid<52 -> (b = tid/13, k = tid%13), scalar per step
    const int pfb = (LAYER == 0) ? ((tid < BC*NI) ? tid/NI : 0) : (tid >> 6);
    const int pfk = (LAYER == 0) ? ((tid < BC*NI) ? tid - pfb*NI : 0) : 2*(tid & 63);
    const float* xpf = xin + ((size_t)(b0 + pfb)*TT + 0)*IN + pfk;
    float pf0 = 0.f, pf1 = 0.f;
    if (LAYER == 0) { if (tid < BC*NI) pf0 = __ldg(xpf); }
    else            { float2 v = __ldg((const float2*)xpf); pf0 = v.x; pf1 = v.y; }

    __syncthreads();

    const ulonglong2* hdq = (const ulonglong2*)hd2;

    for (int t = 0; t < TT; ++t) {
        // ---- phase A: publish this step's input slice (dup-packed) ----
        if (LAYER == 0) {
            if (tid < BC*NI) hd2[pfk*4 + pfb] = dup2(pf0);
        } else {
            hd2[pfk*4 + pfb]     = dup2(pf0);
            hd2[(pfk+1)*4 + pfb] = dup2(pf1);
        }
        __syncthreads();   // covers phase-A writes AND prev-step recurrent-h writes

        // prefetch next step's input (latency hidden behind phase B)
        if (t + 1 < TT) {
            const float* p = xpf + (size_t)(t+1)*IN;
            if (LAYER == 0) { if (tid < BC*NI) pf0 = __ldg(p); }
            else            { float2 v = __ldg((const float2*)p); pf0 = v.x; pf1 = v.y; }
        }

        // ---- phase B: gate pre-activations ----
        ull a0 = bi, a1 = bi, a2 = bi, a3 = bi;

        auto rowfma = [&](ull w, int row){
            ulonglong2 hA = hdq[row*2];
            ulonglong2 hB = hdq[row*2 + 1];
            a0 = ffma2(hA.x, w, a0);  a1 = ffma2(hA.y, w, a1);
            a2 = ffma2(hB.x, w, a2);  a3 = ffma2(hB.y, w, a3);
        };
        auto smemrows = [&](int k0, int n){
            #pragma unroll
            for (int k = 0; k < n; ++k) rowfma(ws2[(k0+k)*256 + tid], k0 + k);
        };

        if (NS > 0) {
            // streamed tier interleaved with smem tier
            const ull* sbase = wt2 + (size_t)S0*256 + tid;
            ull wa[CH], wb[CH];
            auto ldch = [&](ull* buf, int c){
                const ull* p = sbase + (size_t)c*CH*256;
                #pragma unroll
                for (int i = 0; i < CH; ++i) buf[i] = __ldg(p + i*256);
            };
            auto usech = [&](const ull* buf, int c){
                #pragma unroll
                for (int i = 0; i < CH; ++i) rowfma(buf[i], S0 + c*CH + i);
            };

            ldch(wa, 0);                       // issue first chunk early
            #pragma unroll
            for (int r = 0; r < RR; ++r) rowfma(wreg[r], WS + r);   // hides chunk 0

            #pragma unroll 1
            for (int c = 0; c + 2 < NCH; c += 2) {
                ldch(wb, c+1);  usech(wa, c);    smemrows(SEG*c,     SEG);
                ldch(wa, c+2);  usech(wb, c+1);  smemrows(SEG*(c+1), SEG);
            }
            ldch(wb, NCH-1);  usech(wa, NCH-2);  smemrows(SEG*(NCH-2), SEG);
            usech(wb, NCH-1);                    smemrows(SEG*(NCH-1), SEG);
            smemrows(SEG*NCH, WS - SEG*NCH);     // tail smem rows
        } else {
            #pragma unroll
            for (int r = 0; r < RR; ++r) rowfma(wreg[r], WS + r);
            #pragma unroll 8
            for (int k = 0; k < WS; ++k) rowfma(ws2[k*256 + tid], k);
        }

        // ---- phase C: publish gate pre-activations ----
        gs2[0*256 + tid] = a0;
        gs2[1*256 + tid] = a1;
        gs2[2*256 + tid] = a2;
        gs2[3*256 + tid] = a3;
        __syncthreads();

        // ---- phase D: gates + state update (thread -> (dj, 2 batches)) ----
        #pragma unroll
        for (int q = 0; q < 2; ++q) {
            int b = db + q;
            float gi = gsf[b*GG +          dj];
            float gf = gsf[b*GG +   HH  +  dj];
            float gg = gsf[b*GG + 2*HH  +  dj];
            float go = gsf[b*GG + 3*HH  +  dj];
            float ig = sigf(gi);                       // accurate: feeds c integral
            float fg = sigf(gf);                       // accurate
            float gv = tanh_(gg);                      // accurate
            float og = fmaf(tanhap(0.5f*go), 0.5f, 0.5f);  // approx: output path
            float c  = fg*cst[q] + ig*gv;
            cst[q] = c;
            float h = og * tanhap(c);                  // approx: output path
            hd2[(IN + dj)*4 + b] = dup2(h);
            if (LAYER == 0) {
                d_h1[((size_t)(b0 + b)*TT + t)*HH + dj] = h;
            }
        }
        // next iteration's phase-A sync orders D's hd2 writes before the k-loop
    }

    // ---- fused FC epilogue (layer 1 only): out[b][c] = h . Wfc[c] + bfc[c] ----
    if (LAYER == 1) {
        __syncthreads();                   // all final h visible in hd2
        int g = tid >> 4;                  // 16 groups of 16 threads
        int l = tid & 15;
        int b = g >> 2, c = g & 3;
        float s = 0.f;
        #pragma unroll
        for (int q = 0; q < 8; ++q) {
            int j = l + 16*q;
            float hv = ((const float*)(hd2 + (size_t)(IN + j)*4 + b))[0];
            s += hv * __ldg(&Wfc[c*HH + j]);
        }
        #pragma unroll
        for (int o = 8; o; o >>= 1) s += __shfl_xor_sync(0xffffffffu, s, o, 16);
        if (l == 0) out[(b0 + b)*4 + c] = s + __ldg(&bfc[c]);
    }
}

// -------- launch --------
extern "C" void kernel_launch(void* const* d_in, const int* in_sizes, int n_in,
                              void* d_out, int out_size)
{
    const float* x    = (const float*)d_in[0];
    const float* Wih0 = (const float*)d_in[1];
    const float* Whh0 = (const float*)d_in[2];
    const float* bih0 = (const float*)d_in[3];
    const float* bhh0 = (const float*)d_in[4];
    const float* Wih1 = (const float*)d_in[5];
    const float* Whh1 = (const float*)d_in[6];
    const float* bih1 = (const float*)d_in[7];
    const float* bhh1 = (const float*)d_in[8];
    const float* Wfc  = (const float*)d_in[9];
    const float* bfc  = (const float*)d_in[10];
    float* out = (float*)d_out;

    constexpr int K0 = NI + HH, K1 = HH + HH;
    constexpr int SMEM0 = (WS_K*256 + K0*4 + 4*256) * 8;   // 225,696 B
    constexpr int SMEM1 = (WS_K*256 + K1*4 + 4*256) * 8;   // 229,376 B

    cudaFuncSetAttribute(lstm_layer<0>, cudaFuncAttributeMaxDynamicSharedMemorySize, SMEM0);
    cudaFuncSetAttribute(lstm_layer<1>, cudaFuncAttributeMaxDynamicSharedMemorySize, SMEM1);

    prep_kernel<<<256, 256>>>(Wih0, Whh0, bih0, bhh0, Wih1, Whh1, bih1, bhh1);
    lstm_layer<0><<<NBLK, NTHR, SMEM0>>>(x, nullptr, nullptr, nullptr);
    lstm_layer<1><<<NBLK, NTHR, SMEM1>>>(nullptr, Wfc, bfc, out);
}